// round 16
// baseline (speedup 1.0000x reference)
#include <cuda_runtime.h>
#include <cuda_bf16.h>
#include <stdint.h>
#include <string.h>
#include <math.h>

#define B_  16
#define N_  1024
#define D_  256
#define NC_ 2048
#define INV_TEMP 14.285714285714286f

// ---- scratch (device globals; allocations forbidden) ----
__device__ __nv_bfloat16 g_zn[(size_t)B_ * NC_ * D_];
__device__ float         g_sim[(size_t)B_ * N_ * N_];
__device__ __nv_bfloat16 g_A  [(size_t)B_ * N_ * N_];
__device__ __nv_bfloat16 g_AT [(size_t)B_ * N_ * N_];
__device__ __nv_bfloat16 g_A2 [(size_t)B_ * N_ * N_];
__device__ __nv_bfloat16 g_A2T[(size_t)B_ * N_ * N_];
__device__ float         g_P  [(size_t)B_ * N_ * N_];
__device__ float g_topv[2 * B_ * N_ * 5];
__device__ int   g_topi[2 * B_ * N_ * 5];
__device__ float g_den[B_ * NC_];
__device__ float g_partial[4096];

// ---- helpers ----
__device__ __forceinline__ uint32_t smem_to_u32(const void* p) {
    uint32_t a;
    asm("{ .reg .u64 t; cvta.to.shared.u64 t, %1; cvt.u32.u64 %0, t; }" : "=r"(a) : "l"(p));
    return a;
}
__device__ __forceinline__ void cp_async16(uint32_t dst, const void* src) {
    asm volatile("cp.async.cg.shared.global [%0], [%1], 16;" :: "r"(dst), "l"(src) : "memory");
}
#define CP_COMMIT() asm volatile("cp.async.commit_group;" ::: "memory")
#define CP_WAIT(n)  asm volatile("cp.async.wait_group %0;" :: "n"(n) : "memory")

__device__ __forceinline__ void mma16816(float c[4], const uint32_t a[4], const uint32_t b[2]) {
    asm volatile(
        "mma.sync.aligned.m16n8k16.row.col.f32.bf16.bf16.f32 "
        "{%0,%1,%2,%3}, {%4,%5,%6,%7}, {%8,%9}, {%0,%1,%2,%3};\n"
        : "+f"(c[0]), "+f"(c[1]), "+f"(c[2]), "+f"(c[3])
        : "r"(a[0]), "r"(a[1]), "r"(a[2]), "r"(a[3]), "r"(b[0]), "r"(b[1]));
}
__device__ __forceinline__ void ldsm_x4(uint32_t& r0, uint32_t& r1, uint32_t& r2, uint32_t& r3,
                                        uint32_t addr) {
    asm volatile("ldmatrix.sync.aligned.m8n8.x4.shared.b16 {%0,%1,%2,%3}, [%4];"
                 : "=r"(r0), "=r"(r1), "=r"(r2), "=r"(r3) : "r"(addr));
}

// ======== pipelined bf16 HMMA GEMM ==========================================
// CTA tile 128x128, 4 warps (2x2), 64x64 warp tiles, 128 threads/CTA.
// 32-K chunks, 4-stage cp.async. Crossbar bytes/FLOP cut 1.5x vs 32x64 tiles.
#define GBM 128
#define GBN 128
#define GBK 32
#define GBKP 40                      // pad: LDSM row banks = r*20%32, conflict-free
#define STG 4
#define ABYTES (GBM * GBKP * 2)      // 10240
#define STAGE_BYTES (2 * ABYTES)     // A + B = 20480
#define GEMM_SMEM (STG * STAGE_BYTES) // 81920
#define GTHR 128

// MODE 0: f32 C store | MODE 1: bf16 C store + P += | MODE 2: P += only
// A: [M,K] k-major rows; B: [N,K] k-major rows (pre-transposed where needed)
template<int MODE>
__global__ void __launch_bounds__(GTHR)
pg_gemm(const __nv_bfloat16* __restrict__ Ag, size_t sA,
        const __nv_bfloat16* __restrict__ Bg, size_t sB,
        float* __restrict__ Cf, __nv_bfloat16* __restrict__ Cb, float* __restrict__ Pf,
        size_t sC, int KD, int Ncols)
{
    extern __shared__ __align__(16) char smem[];
    const uint32_t sbase = smem_to_u32(smem);
    const int tid = threadIdx.x;
    const int wid = tid >> 5, lane = tid & 31;
    const int wm = wid >> 1, wn = wid & 1;          // 2x2 warp grid
    const int gid = lane >> 2, t4 = lane & 3;
    const int bx = blockIdx.x, by = blockIdx.y, bz = blockIdx.z;
    const __nv_bfloat16* Ab = Ag + (size_t)bz * sA + (size_t)(by * GBM) * KD;
    const __nv_bfloat16* Bb = Bg + (size_t)bz * sB + (size_t)(bx * GBN) * KD;
    const int NCHUNK = KD / GBK;

    // ldmatrix per-thread address components (validated in R14)
    const int a_row_l = (lane & 15);
    const int a_colo  = (lane & 16) ? 8 : 0;
    const int b_row_l = (lane & 7) + ((lane & 16) ? 8 : 0);
    const int b_colo  = (lane & 8) ? 8 : 0;

    // cp.async: each of 128 threads copies one full 64B row of A and of B
    auto issue_chunk = [&](int c) {
        const int kb = c * GBK;
        const uint32_t st = sbase + (c % STG) * STAGE_BYTES;
        #pragma unroll
        for (int c16 = 0; c16 < 4; c16++) {
            uint32_t off = (uint32_t)tid * (GBKP * 2) + c16 * 16;
            cp_async16(st + off,          Ab + (size_t)tid * KD + kb + c16 * 8);
            cp_async16(st + ABYTES + off, Bb + (size_t)tid * KD + kb + c16 * 8);
        }
    };

    float acc[4][8][4];
    #pragma unroll
    for (int mi = 0; mi < 4; mi++)
        #pragma unroll
        for (int ni = 0; ni < 8; ni++)
            #pragma unroll
            for (int q = 0; q < 4; q++) acc[mi][ni][q] = 0.f;

    #pragma unroll
    for (int k = 0; k < STG - 1; k++) {
        if (k < NCHUNK) issue_chunk(k);
        CP_COMMIT();
    }

    for (int c = 0; c < NCHUNK; c++) {
        __syncthreads();
        if (c + STG - 1 < NCHUNK) issue_chunk(c + STG - 1);
        CP_COMMIT();
        CP_WAIT(STG - 1);
        __syncthreads();

        const uint32_t Asu = sbase + (c % STG) * STAGE_BYTES;
        const uint32_t Bsu = Asu + ABYTES;
        #pragma unroll
        for (int kk = 0; kk < 2; kk++) {
            uint32_t af[4][4], bfr[8][2];
            const int acol = kk * 16 + a_colo;
            const int bcol = kk * 16 + b_colo;
            #pragma unroll
            for (int mi = 0; mi < 4; mi++) {
                int r = wm * 64 + mi * 16 + a_row_l;
                ldsm_x4(af[mi][0], af[mi][1], af[mi][2], af[mi][3],
                        Asu + (uint32_t)r * (GBKP * 2) + acol * 2);
            }
            #pragma unroll
            for (int p = 0; p < 4; p++) {
                int n = wn * 64 + p * 16 + b_row_l;
                ldsm_x4(bfr[2*p][0], bfr[2*p][1], bfr[2*p+1][0], bfr[2*p+1][1],
                        Bsu + (uint32_t)n * (GBKP * 2) + bcol * 2);
            }
            #pragma unroll
            for (int mi = 0; mi < 4; mi++)
                #pragma unroll
                for (int ni = 0; ni < 8; ni++)
                    mma16816(acc[mi][ni], af[mi], bfr[ni]);
        }
    }

    #pragma unroll
    for (int mi = 0; mi < 4; mi++) {
        #pragma unroll
        for (int ni = 0; ni < 8; ni++) {
            int r0 = by * GBM + wm * 64 + mi * 16 + gid;
            int c0 = bx * GBN + wn * 64 + ni * 8 + 2 * t4;
            size_t base  = (size_t)bz * sC + (size_t)r0 * Ncols + c0;
            size_t base8 = base + (size_t)8 * Ncols;
            float* a4 = acc[mi][ni];
            if (MODE == 0) {
                Cf[base] = a4[0];  Cf[base + 1] = a4[1];
                Cf[base8] = a4[2]; Cf[base8 + 1] = a4[3];
            } else if (MODE == 1) {
                *reinterpret_cast<__nv_bfloat162*>(Cb + base)  = __floats2bfloat162_rn(a4[0], a4[1]);
                *reinterpret_cast<__nv_bfloat162*>(Cb + base8) = __floats2bfloat162_rn(a4[2], a4[3]);
                Pf[base]  += a4[0]; Pf[base + 1]  += a4[1];
                Pf[base8] += a4[2]; Pf[base8 + 1] += a4[3];
            } else {
                Pf[base]  += a4[0]; Pf[base + 1]  += a4[1];
                Pf[base8] += a4[2]; Pf[base8 + 1] += a4[3];
            }
        }
    }
}

// ---- no-op launch to shift ncu's -s 5 window onto pg_gemm<1> ----
__global__ void nop_kernel() {}

// ======== bf16 batched transpose (64x64 tiles) ==============================
__global__ void __launch_bounds__(256) transpose_kernel(
    const __nv_bfloat16* __restrict__ src, __nv_bfloat16* __restrict__ dst)
{
    __shared__ __nv_bfloat16 t[64][72];
    const int bx = blockIdx.x, by = blockIdx.y, bz = blockIdx.z;
    const __nv_bfloat16* s = src + (size_t)bz * N_ * N_;
    __nv_bfloat16* d = dst + (size_t)bz * N_ * N_;
    const int tid = threadIdx.x;
    #pragma unroll
    for (int i = 0; i < 2; i++) {
        int e = tid + i * 256;
        int r = e >> 3, c8 = e & 7;
        uint4 v = *reinterpret_cast<const uint4*>(s + (size_t)(by * 64 + r) * N_ + bx * 64 + c8 * 8);
        *reinterpret_cast<uint4*>(&t[r][c8 * 8]) = v;
    }
    __syncthreads();
    #pragma unroll
    for (int i = 0; i < 2; i++) {
        int e = tid + i * 256;
        int r = e >> 3, c8 = e & 7;
        __nv_bfloat16 tmp[8];
        #pragma unroll
        for (int j = 0; j < 8; j++) tmp[j] = t[c8 * 8 + j][r];
        uint4 v; memcpy(&v, tmp, 16);
        *reinterpret_cast<uint4*>(d + (size_t)(bx * 64 + r) * N_ + by * 64 + c8 * 8) = v;
    }
}

// ---- normalize concat rows -> bf16 ----
__global__ void norm_kernel(const float* __restrict__ z1, const float* __restrict__ z2) {
    int warp = (blockIdx.x * blockDim.x + threadIdx.x) >> 5;
    int lane = threadIdx.x & 31;
    int b = warp >> 11;
    int i = warp & (NC_ - 1);
    const float* src = (i < N_) ? z1 + ((size_t)b * N_ + i) * D_
                                : z2 + ((size_t)b * N_ + (i - N_)) * D_;
    float4 v0 = reinterpret_cast<const float4*>(src)[2 * lane + 0];
    float4 v1 = reinterpret_cast<const float4*>(src)[2 * lane + 1];
    float s = v0.x*v0.x + v0.y*v0.y + v0.z*v0.z + v0.w*v0.w
            + v1.x*v1.x + v1.y*v1.y + v1.z*v1.z + v1.w*v1.w;
    #pragma unroll
    for (int off = 16; off; off >>= 1) s += __shfl_xor_sync(0xffffffffu, s, off);
    float sc = 1.0f / (sqrtf(s) + 1e-12f);
    __nv_bfloat162 o[4];
    o[0] = __floats2bfloat162_rn(v0.x*sc, v0.y*sc);
    o[1] = __floats2bfloat162_rn(v0.z*sc, v0.w*sc);
    o[2] = __floats2bfloat162_rn(v1.x*sc, v1.y*sc);
    o[3] = __floats2bfloat162_rn(v1.z*sc, v1.w*sc);
    uint4 pk; memcpy(&pk, o, 16);
    reinterpret_cast<uint4*>(g_zn + ((size_t)b * NC_ + i) * D_)[lane] = pk;
}

// ---- softmax rows: g_sim -> g_A (bf16), g_P = A ----
__global__ void softmax_kernel() {
    int warp = (blockIdx.x * blockDim.x + threadIdx.x) >> 5;
    int lane = threadIdx.x & 31;
    const float* row = g_sim + (size_t)warp * N_;
    float x[32];
    #pragma unroll
    for (int k = 0; k < 32; k++) x[k] = row[k * 32 + lane];
    float mx = x[0];
    #pragma unroll
    for (int k = 1; k < 32; k++) mx = fmaxf(mx, x[k]);
    #pragma unroll
    for (int off = 16; off; off >>= 1) mx = fmaxf(mx, __shfl_xor_sync(0xffffffffu, mx, off));
    float s = 0.f;
    #pragma unroll
    for (int k = 0; k < 32; k++) { x[k] = __expf(x[k] - mx); s += x[k]; }
    #pragma unroll
    for (int off = 16; off; off >>= 1) s += __shfl_xor_sync(0xffffffffu, s, off);
    float inv = 1.0f / s;
    __nv_bfloat16* arow = g_A + (size_t)warp * N_;
    float* prow = g_P + (size_t)warp * N_;
    #pragma unroll
    for (int k = 0; k < 32; k++) {
        float p = x[k] * inv;
        prow[k * 32 + lane] = p;
        arow[k * 32 + lane] = __float2bfloat16(p);
    }
}

// ---- top-5 of scores = 0.5*pw + P/6 ----
__global__ void topk_kernel(int v) {
    int lwarp = threadIdx.x >> 5;
    int lane  = threadIdx.x & 31;
    int row = blockIdx.x * 8 + lwarp;
    int i = row & (N_ - 1);
    const float* Prow = g_P + (size_t)row * N_;
    float tv[5] = {-1e30f, -1e30f, -1e30f, -1e30f, -1e30f};
    int   ti[5] = {0x7fffffff, 0x7fffffff, 0x7fffffff, 0x7fffffff, 0x7fffffff};
    for (int j = lane; j < N_; j += 32) {
        float d = (float)(i - j);
        float s = 0.5f * __expf(-d * d * 0.125f) + Prow[j] * (1.0f / 6.0f);
        if (s > tv[4]) {
            tv[4] = s; ti[4] = j;
            #pragma unroll
            for (int k = 4; k > 0; k--) {
                if (tv[k] > tv[k-1] || (tv[k] == tv[k-1] && ti[k] < ti[k-1])) {
                    float tf = tv[k]; tv[k] = tv[k-1]; tv[k-1] = tf;
                    int   tt = ti[k]; ti[k] = ti[k-1]; ti[k-1] = tt;
                }
            }
        }
    }
    int pos = 0;
    for (int r = 0; r < 5; r++) {
        float cv = (pos < 5) ? tv[pos] : -1e30f;
        int   ci = (pos < 5) ? ti[pos] : 0x7fffffff;
        float wv = cv; int wi = ci;
        #pragma unroll
        for (int off = 16; off; off >>= 1) {
            float ov = __shfl_xor_sync(0xffffffffu, wv, off);
            int   oi = __shfl_xor_sync(0xffffffffu, wi, off);
            if (ov > wv || (ov == wv && oi < wi)) { wv = ov; wi = oi; }
        }
        if (pos < 5 && ci == wi) pos++;
        if (lane == 0) {
            size_t o = ((size_t)v * B_ * N_ + row) * 5 + r;
            g_topv[o] = wv; g_topi[o] = wi;
        }
    }
}

// ---- den: fused exp rowsum over concat, diag excluded exactly (R14 form) ---
#define DWKP 40
__global__ void __launch_bounds__(256) den_kernel() {
    __shared__ __align__(16) __nv_bfloat16 As[GBM][DWKP];
    __shared__ __align__(16) __nv_bfloat16 Bs[GBN][DWKP];
    __shared__ float rsm[2][GBM];
    const int tid = threadIdx.x;
    const int wid = tid >> 5, lane = tid & 31;
    const int wm = wid >> 1, wn = wid & 1;
    const int gid = lane >> 2, t4 = lane & 3;
    const int by = blockIdx.x, bz = blockIdx.y;
    const __nv_bfloat16* Zb = g_zn + (size_t)bz * NC_ * D_;
    const uint32_t uAs = smem_to_u32(&As[0][0]);
    const uint32_t uBs = smem_to_u32(&Bs[0][0]);
    const int a_row_l = (lane & 15);
    const int a_colo  = (lane & 16) ? 8 : 0;
    const int b_row_l = (lane & 7) + ((lane & 16) ? 8 : 0);
    const int b_colo  = (lane & 8) ? 8 : 0;
    float rs[2][2] = {{0.f, 0.f}, {0.f, 0.f}};

    for (int jt = 0; jt < NC_ / GBN; jt++) {
        float acc[2][8][4];
        #pragma unroll
        for (int mi = 0; mi < 2; mi++)
            #pragma unroll
            for (int ni = 0; ni < 8; ni++)
                #pragma unroll
                for (int q = 0; q < 4; q++) acc[mi][ni][q] = 0.f;
        for (int kb = 0; kb < D_; kb += GBK) {
            #pragma unroll
            for (int u = 0; u < 2; u++) {
                int e = tid + u * 256;
                int r = e >> 2, c8 = e & 3;
                *reinterpret_cast<uint4*>(&As[r][c8 * 8]) =
                    *reinterpret_cast<const uint4*>(Zb + (size_t)(by * GBM + r) * D_ + kb + c8 * 8);
                *reinterpret_cast<uint4*>(&Bs[r][c8 * 8]) =
                    *reinterpret_cast<const uint4*>(Zb + (size_t)(jt * GBN + r) * D_ + kb + c8 * 8);
            }
            __syncthreads();
            #pragma unroll
            for (int kk = 0; kk < 2; kk++) {
                uint32_t af[2][4], bfr[8][2];
                const int acol = kk * 16 + a_colo;
                const int bcol = kk * 16 + b_colo;
                #pragma unroll
                for (int mi = 0; mi < 2; mi++) {
                    int r = wm * 32 + mi * 16 + a_row_l;
                    ldsm_x4(af[mi][0], af[mi][1], af[mi][2], af[mi][3],
                            uAs + (uint32_t)r * (DWKP * 2) + acol * 2);
                }
                #pragma unroll
                for (int p = 0; p < 4; p++) {
                    int n = wn * 64 + p * 16 + b_row_l;
                    ldsm_x4(bfr[2*p][0], bfr[2*p][1], bfr[2*p+1][0], bfr[2*p+1][1],
                            uBs + (uint32_t)n * (DWKP * 2) + bcol * 2);
                }
                #pragma unroll
                for (int mi = 0; mi < 2; mi++)
                    #pragma unroll
                    for (int ni = 0; ni < 8; ni++)
                        mma16816(acc[mi][ni], af[mi], bfr[ni]);
            }
            __syncthreads();
        }
        #pragma unroll
        for (int mi = 0; mi < 2; mi++) {
            int rg0 = by * GBM + wm * 32 + mi * 16 + gid;
            #pragma unroll
            for (int ni = 0; ni < 8; ni++) {
                int c0 = jt * GBN + wn * 64 + ni * 8 + 2 * t4;
                if (rg0 != c0)         rs[mi][0] += __expf(acc[mi][ni][0] * INV_TEMP);
                if (rg0 != c0 + 1)     rs[mi][0] += __expf(acc[mi][ni][1] * INV_TEMP);
                if (rg0 + 8 != c0)     rs[mi][1] += __expf(acc[mi][ni][2] * INV_TEMP);
                if (rg0 + 8 != c0 + 1) rs[mi][1] += __expf(acc[mi][ni][3] * INV_TEMP);
            }
        }
    }
    #pragma unroll
    for (int off = 1; off < 4; off <<= 1) {
        rs[0][0] += __shfl_xor_sync(0xffffffffu, rs[0][0], off);
        rs[0][1] += __shfl_xor_sync(0xffffffffu, rs[0][1], off);
        rs[1][0] += __shfl_xor_sync(0xffffffffu, rs[1][0], off);
        rs[1][1] += __shfl_xor_sync(0xffffffffu, rs[1][1], off);
    }
    if (t4 == 0) {
        #pragma unroll
        for (int mi = 0; mi < 2; mi++) {
            rsm[wn][wm * 32 + mi * 16 + gid]     = rs[mi][0];
            rsm[wn][wm * 32 + mi * 16 + gid + 8] = rs[mi][1];
        }
    }
    __syncthreads();
    if (tid < GBM) g_den[bz * NC_ + by * GBM + tid] = rsm[0][tid] + rsm[1][tid];
}

// ---- per-row loss (warp per row), block partial sums ----
__global__ void loss_kernel() {
    __shared__ float wloss[8];
    int lwarp = threadIdx.x >> 5;
    int warp = blockIdx.x * 8 + lwarp;
    int lane = threadIdx.x & 31;
    int b = warp >> 11;
    int i = warp & (NC_ - 1);
    bool half0 = i < N_;
    int ii = half0 ? i : i - N_;
    const __nv_bfloat16* self  = g_zn + ((size_t)b * NC_ + i) * D_;
    const __nv_bfloat16* pbase = g_zn + ((size_t)b * NC_ + (half0 ? N_ : 0)) * D_;
    int v = half0 ? 1 : 0;
    size_t to = (((size_t)v * B_ + b) * N_ + ii) * 5;

    uint4 sv = reinterpret_cast<const uint4*>(self)[lane];
    __nv_bfloat16 ah[8]; memcpy(ah, &sv, 16);
    float af[8];
    #pragma unroll
    for (int k = 0; k < 8; k++) af[k] = __bfloat162float(ah[k]);

    float num = 0.f;
    #pragma unroll
    for (int t = 0; t < 6; t++) {
        int pr; float w;
        if (t == 0) { pr = ii; w = 1.f; }
        else        { pr = g_topi[to + t - 1]; w = g_topv[to + t - 1]; }
        uint4 bv = reinterpret_cast<const uint4*>(pbase + (size_t)pr * D_)[lane];
        __nv_bfloat16 bh[8]; memcpy(bh, &bv, 16);
        float s = 0.f;
        #pragma unroll
        for (int k = 0; k < 8; k++) s += af[k] * __bfloat162float(bh[k]);
        #pragma unroll
        for (int off = 16; off; off >>= 1) s += __shfl_xor_sync(0xffffffffu, s, off);
        float e = expf(s * INV_TEMP);
        if (t == 0) num += e;
        else if (pr != ii) num += w * e;
    }
    if (lane == 0) {
        float den = g_den[b * NC_ + i];
        wloss[lwarp] = -logf(num / (den + 1e-9f) + 1e-9f);
    }
    __syncthreads();
    if (threadIdx.x == 0) {
        float s = 0.f;
        #pragma unroll
        for (int k = 0; k < 8; k++) s += wloss[k];
        g_partial[blockIdx.x] = s;
    }
}

__global__ void reduce_kernel(float* out) {
    int tid = threadIdx.x;
    float s = 0.f;
    for (int k = tid; k < 4096; k += 256) s += g_partial[k];
    #pragma unroll
    for (int off = 16; off; off >>= 1) s += __shfl_xor_sync(0xffffffffu, s, off);
    __shared__ float sm[8];
    if ((tid & 31) == 0) sm[tid >> 5] = s;
    __syncthreads();
    if (tid == 0) {
        float t = 0.f;
        #pragma unroll
        for (int k = 0; k < 8; k++) t += sm[k];
        out[0] = t / (float)(B_ * NC_);
    }
}

// ======================= launch =============================================
extern "C" void kernel_launch(void* const* d_in, const int* in_sizes, int n_in,
                              void* d_out, int out_size) {
    const float* z1 = (const float*)d_in[0];
    const float* z2 = (const float*)d_in[1];
    float* out = (float*)d_out;
    (void)in_sizes; (void)n_in; (void)out_size;

    cudaFuncSetAttribute(pg_gemm<0>, cudaFuncAttributeMaxDynamicSharedMemorySize, GEMM_SMEM);
    cudaFuncSetAttribute(pg_gemm<1>, cudaFuncAttributeMaxDynamicSharedMemorySize, GEMM_SMEM);
    cudaFuncSetAttribute(pg_gemm<2>, cudaFuncAttributeMaxDynamicSharedMemorySize, GEMM_SMEM);

    __nv_bfloat16* znA = nullptr;
    float *simP = nullptr, *pP = nullptr;
    __nv_bfloat16 *aP = nullptr, *atP = nullptr, *a2P = nullptr, *a2tP = nullptr;
    cudaGetSymbolAddress((void**)&znA,  g_zn);
    cudaGetSymbolAddress((void**)&simP, g_sim);
    cudaGetSymbolAddress((void**)&aP,   g_A);
    cudaGetSymbolAddress((void**)&atP,  g_AT);
    cudaGetSymbolAddress((void**)&a2P,  g_A2);
    cudaGetSymbolAddress((void**)&a2tP, g_A2T);
    cudaGetSymbolAddress((void**)&pP,   g_P);

    norm_kernel<<<4096, 256>>>(z1, z2);
    nop_kernel<<<1, 32>>>();   // shifts ncu -s 5 window onto pg_gemm<1>
    dim3 gg(N_ / GBN, N_ / GBM, B_);
    dim3 gt(16, 16, B_);
    for (int v = 0; v < 2; v++) {
        const __nv_bfloat16* zv = znA + (size_t)v * N_ * D_;
        pg_gemm<0><<<gg, GTHR, GEMM_SMEM>>>(zv, (size_t)NC_ * D_, zv, (size_t)NC_ * D_,
                                            simP, nullptr, nullptr, (size_t)N_ * N_, D_, N_);
        softmax_kernel<<<2048, 256>>>();
        transpose_kernel<<<gt, 256>>>(aP, atP);
        pg_gemm<1><<<gg, GTHR, GEMM_SMEM>>>(aP, (size_t)N_ * N_, atP, (size_t)N_ * N_,
                                            nullptr, a2P, pP, (size_t)N_ * N_, N_, N_);
        transpose_kernel<<<gt, 256>>>(a2P, a2tP);
        pg_gemm<2><<<gg, GTHR, GEMM_SMEM>>>(a2P, (size_t)N_ * N_, a2tP, (size_t)N_ * N_,
                                            nullptr, nullptr, pP, (size_t)N_ * N_, N_, N_);
        topk_kernel<<<2048, 256>>>(v);
    }
    den_kernel<<<dim3(NC_ / GBM, B_), 256>>>();
    loss_kernel<<<4096, 256>>>();
    reduce_kernel<<<1, 256>>>(out);
}

// round 17
// speedup vs baseline: 1.3739x; 1.3739x over previous
#include <cuda_runtime.h>
#include <cuda_bf16.h>
#include <stdint.h>
#include <string.h>
#include <math.h>

#define B_  16
#define N_  1024
#define D_  256
#define NC_ 2048
#define INV_TEMP 14.285714285714286f

// ---- scratch (device globals; allocations forbidden) ----
__device__ __nv_bfloat16 g_zn[(size_t)B_ * NC_ * D_];
__device__ float         g_sim[(size_t)B_ * N_ * N_];
__device__ __nv_bfloat16 g_A  [(size_t)B_ * N_ * N_];
__device__ __nv_bfloat16 g_AT [(size_t)B_ * N_ * N_];
__device__ __nv_bfloat16 g_A2 [(size_t)B_ * N_ * N_];
__device__ __nv_bfloat16 g_A2T[(size_t)B_ * N_ * N_];
__device__ float         g_P  [(size_t)B_ * N_ * N_];
__device__ float g_topv[2 * B_ * N_ * 5];
__device__ int   g_topi[2 * B_ * N_ * 5];
__device__ float g_den[B_ * NC_];
__device__ float g_partial[4096];

// ---- helpers ----
__device__ __forceinline__ uint32_t smem_to_u32(const void* p) {
    uint32_t a;
    asm("{ .reg .u64 t; cvta.to.shared.u64 t, %1; cvt.u32.u64 %0, t; }" : "=r"(a) : "l"(p));
    return a;
}
__device__ __forceinline__ void cp_async16(uint32_t dst, const void* src) {
    asm volatile("cp.async.cg.shared.global [%0], [%1], 16;" :: "r"(dst), "l"(src) : "memory");
}
#define CP_COMMIT() asm volatile("cp.async.commit_group;" ::: "memory")
#define CP_WAIT(n)  asm volatile("cp.async.wait_group %0;" :: "n"(n) : "memory")

__device__ __forceinline__ void mma16816(float c[4], const uint32_t a[4], const uint32_t b[2]) {
    asm volatile(
        "mma.sync.aligned.m16n8k16.row.col.f32.bf16.bf16.f32 "
        "{%0,%1,%2,%3}, {%4,%5,%6,%7}, {%8,%9}, {%0,%1,%2,%3};\n"
        : "+f"(c[0]), "+f"(c[1]), "+f"(c[2]), "+f"(c[3])
        : "r"(a[0]), "r"(a[1]), "r"(a[2]), "r"(a[3]), "r"(b[0]), "r"(b[1]));
}

// ======== pipelined bf16 HMMA GEMM: 128x128 CTA tile (R5 core, 1 sync/chunk)
#define GBM 128
#define GBN 128
#define GBK 32
#define GBKP 40                      // pad: bank = (20*gid + t4) % 32, conflict-free
#define STG 4
#define ABYTES (GBM * GBKP * 2)      // 10240
#define STAGE_BYTES (2 * ABYTES)     // A + B = 20480
#define GEMM_SMEM (STG * STAGE_BYTES) // 81920

// MODE 0: f32 C store | MODE 1: bf16 C store + P += | MODE 2: P += only
// A: [M,K] k-major rows; B: [N,K] k-major rows (pre-transposed where needed)
template<int MODE>
__global__ void __launch_bounds__(256)
pg_gemm(const __nv_bfloat16* __restrict__ Ag, size_t sA,
        const __nv_bfloat16* __restrict__ Bg, size_t sB,
        float* __restrict__ Cf, __nv_bfloat16* __restrict__ Cb, float* __restrict__ Pf,
        size_t sC, int KD, int Ncols)
{
    extern __shared__ __align__(16) char smem[];
    const uint32_t sbase = smem_to_u32(smem);
    const int tid = threadIdx.x;
    const int wid = tid >> 5, lane = tid & 31;
    const int wm = wid >> 1, wn = wid & 1;
    const int gid = lane >> 2, t4 = lane & 3;
    const int bx = blockIdx.x, by = blockIdx.y, bz = blockIdx.z;
    const __nv_bfloat16* Ab = Ag + (size_t)bz * sA + (size_t)(by * GBM) * KD;
    const __nv_bfloat16* Bb = Bg + (size_t)bz * sB + (size_t)(bx * GBN) * KD;
    const int NCHUNK = KD / GBK;

    const int cr  = tid >> 1;
    const int cc16 = tid & 1;
    auto issue_chunk = [&](int c) {
        const int kb = c * GBK;
        const uint32_t st = sbase + (c % STG) * STAGE_BYTES;
        #pragma unroll
        for (int h = 0; h < 2; h++) {
            int c16 = cc16 * 2 + h;
            uint32_t off = (uint32_t)cr * (GBKP * 2) + c16 * 16;
            cp_async16(st + off,          Ab + (size_t)cr * KD + kb + c16 * 8);
            cp_async16(st + ABYTES + off, Bb + (size_t)cr * KD + kb + c16 * 8);
        }
    };

    float acc[2][8][4];
    #pragma unroll
    for (int mi = 0; mi < 2; mi++)
        #pragma unroll
        for (int ni = 0; ni < 8; ni++)
            #pragma unroll
            for (int q = 0; q < 4; q++) acc[mi][ni][q] = 0.f;

    #pragma unroll
    for (int k = 0; k < STG - 1; k++) {
        if (k < NCHUNK) issue_chunk(k);
        CP_COMMIT();
    }

    for (int c = 0; c < NCHUNK; c++) {
        CP_WAIT(STG - 2);            // this thread's chunk-c copies done
        __syncthreads();             // publish chunk c; proves all warps done with c-1
        if (c + STG - 1 < NCHUNK) issue_chunk(c + STG - 1);  // into freed stage
        CP_COMMIT();

        const char* st = smem + (c % STG) * STAGE_BYTES;
        const __nv_bfloat16* As = reinterpret_cast<const __nv_bfloat16*>(st);
        const __nv_bfloat16* Bs = reinterpret_cast<const __nv_bfloat16*>(st + ABYTES);
        #pragma unroll
        for (int kk = 0; kk < 2; kk++) {
            uint32_t af[2][4], bfr[8][2];
            const int ccol = kk * 16 + 2 * t4;
            #pragma unroll
            for (int mi = 0; mi < 2; mi++) {
                int r = wm * 32 + mi * 16 + gid;
                af[mi][0] = *reinterpret_cast<const uint32_t*>(As + r * GBKP + ccol);
                af[mi][1] = *reinterpret_cast<const uint32_t*>(As + (r + 8) * GBKP + ccol);
                af[mi][2] = *reinterpret_cast<const uint32_t*>(As + r * GBKP + ccol + 8);
                af[mi][3] = *reinterpret_cast<const uint32_t*>(As + (r + 8) * GBKP + ccol + 8);
            }
            #pragma unroll
            for (int ni = 0; ni < 8; ni++) {
                int n = wn * 64 + ni * 8 + gid;
                bfr[ni][0] = *reinterpret_cast<const uint32_t*>(Bs + n * GBKP + ccol);
                bfr[ni][1] = *reinterpret_cast<const uint32_t*>(Bs + n * GBKP + ccol + 8);
            }
            #pragma unroll
            for (int mi = 0; mi < 2; mi++)
                #pragma unroll
                for (int ni = 0; ni < 8; ni++)
                    mma16816(acc[mi][ni], af[mi], bfr[ni]);
        }
    }

    #pragma unroll
    for (int mi = 0; mi < 2; mi++) {
        #pragma unroll
        for (int ni = 0; ni < 8; ni++) {
            int r0 = by * GBM + wm * 32 + mi * 16 + gid;
            int c0 = bx * GBN + wn * 64 + ni * 8 + 2 * t4;
            size_t base  = (size_t)bz * sC + (size_t)r0 * Ncols + c0;
            size_t base8 = base + (size_t)8 * Ncols;
            float* a4 = acc[mi][ni];
            if (MODE == 0) {
                Cf[base] = a4[0];  Cf[base + 1] = a4[1];
                Cf[base8] = a4[2]; Cf[base8 + 1] = a4[3];
            } else if (MODE == 1) {
                *reinterpret_cast<__nv_bfloat162*>(Cb + base)  = __floats2bfloat162_rn(a4[0], a4[1]);
                *reinterpret_cast<__nv_bfloat162*>(Cb + base8) = __floats2bfloat162_rn(a4[2], a4[3]);
                Pf[base]  += a4[0]; Pf[base + 1]  += a4[1];
                Pf[base8] += a4[2]; Pf[base8 + 1] += a4[3];
            } else {
                Pf[base]  += a4[0]; Pf[base + 1]  += a4[1];
                Pf[base8] += a4[2]; Pf[base8 + 1] += a4[3];
            }
        }
    }
}

// ---- tiny kernels ----
__global__ void nop_kernel() {}
__global__ void zden_kernel() {
    int i = blockIdx.x * blockDim.x + threadIdx.x;
    if (i < B_ * NC_) g_den[i] = 0.f;
}

// ======== bf16 batched transpose (64x64 tiles) ==============================
__global__ void __launch_bounds__(256) transpose_kernel(
    const __nv_bfloat16* __restrict__ src, __nv_bfloat16* __restrict__ dst)
{
    __shared__ __nv_bfloat16 t[64][72];
    const int bx = blockIdx.x, by = blockIdx.y, bz = blockIdx.z;
    const __nv_bfloat16* s = src + (size_t)bz * N_ * N_;
    __nv_bfloat16* d = dst + (size_t)bz * N_ * N_;
    const int tid = threadIdx.x;
    #pragma unroll
    for (int i = 0; i < 2; i++) {
        int e = tid + i * 256;
        int r = e >> 3, c8 = e & 7;
        uint4 v = *reinterpret_cast<const uint4*>(s + (size_t)(by * 64 + r) * N_ + bx * 64 + c8 * 8);
        *reinterpret_cast<uint4*>(&t[r][c8 * 8]) = v;
    }
    __syncthreads();
    #pragma unroll
    for (int i = 0; i < 2; i++) {
        int e = tid + i * 256;
        int r = e >> 3, c8 = e & 7;
        __nv_bfloat16 tmp[8];
        #pragma unroll
        for (int j = 0; j < 8; j++) tmp[j] = t[c8 * 8 + j][r];
        uint4 v; memcpy(&v, tmp, 16);
        *reinterpret_cast<uint4*>(d + (size_t)(bx * 64 + r) * N_ + by * 64 + c8 * 8) = v;
    }
}

// ---- normalize concat rows -> bf16 ----
__global__ void norm_kernel(const float* __restrict__ z1, const float* __restrict__ z2) {
    int warp = (blockIdx.x * blockDim.x + threadIdx.x) >> 5;
    int lane = threadIdx.x & 31;
    int b = warp >> 11;
    int i = warp & (NC_ - 1);
    const float* src = (i < N_) ? z1 + ((size_t)b * N_ + i) * D_
                                : z2 + ((size_t)b * N_ + (i - N_)) * D_;
    float4 v0 = reinterpret_cast<const float4*>(src)[2 * lane + 0];
    float4 v1 = reinterpret_cast<const float4*>(src)[2 * lane + 1];
    float s = v0.x*v0.x + v0.y*v0.y + v0.z*v0.z + v0.w*v0.w
            + v1.x*v1.x + v1.y*v1.y + v1.z*v1.z + v1.w*v1.w;
    #pragma unroll
    for (int off = 16; off; off >>= 1) s += __shfl_xor_sync(0xffffffffu, s, off);
    float sc = 1.0f / (sqrtf(s) + 1e-12f);
    __nv_bfloat162 o[4];
    o[0] = __floats2bfloat162_rn(v0.x*sc, v0.y*sc);
    o[1] = __floats2bfloat162_rn(v0.z*sc, v0.w*sc);
    o[2] = __floats2bfloat162_rn(v1.x*sc, v1.y*sc);
    o[3] = __floats2bfloat162_rn(v1.z*sc, v1.w*sc);
    uint4 pk; memcpy(&pk, o, 16);
    reinterpret_cast<uint4*>(g_zn + ((size_t)b * NC_ + i) * D_)[lane] = pk;
}

// ---- softmax rows: g_sim -> g_A (bf16), g_P = A ----
__global__ void softmax_kernel() {
    int warp = (blockIdx.x * blockDim.x + threadIdx.x) >> 5;
    int lane = threadIdx.x & 31;
    const float* row = g_sim + (size_t)warp * N_;
    float x[32];
    #pragma unroll
    for (int k = 0; k < 32; k++) x[k] = row[k * 32 + lane];
    float mx = x[0];
    #pragma unroll
    for (int k = 1; k < 32; k++) mx = fmaxf(mx, x[k]);
    #pragma unroll
    for (int off = 16; off; off >>= 1) mx = fmaxf(mx, __shfl_xor_sync(0xffffffffu, mx, off));
    float s = 0.f;
    #pragma unroll
    for (int k = 0; k < 32; k++) { x[k] = __expf(x[k] - mx); s += x[k]; }
    #pragma unroll
    for (int off = 16; off; off >>= 1) s += __shfl_xor_sync(0xffffffffu, s, off);
    float inv = 1.0f / s;
    __nv_bfloat16* arow = g_A + (size_t)warp * N_;
    float* prow = g_P + (size_t)warp * N_;
    #pragma unroll
    for (int k = 0; k < 32; k++) {
        float p = x[k] * inv;
        prow[k * 32 + lane] = p;
        arow[k * 32 + lane] = __float2bfloat16(p);
    }
}

// ---- top-5 of scores = 0.5*pw + P/6 ----
__global__ void topk_kernel(int v) {
    int lwarp = threadIdx.x >> 5;
    int lane  = threadIdx.x & 31;
    int row = blockIdx.x * 8 + lwarp;
    int i = row & (N_ - 1);
    const float* Prow = g_P + (size_t)row * N_;
    float tv[5] = {-1e30f, -1e30f, -1e30f, -1e30f, -1e30f};
    int   ti[5] = {0x7fffffff, 0x7fffffff, 0x7fffffff, 0x7fffffff, 0x7fffffff};
    for (int j = lane; j < N_; j += 32) {
        float d = (float)(i - j);
        float s = 0.5f * __expf(-d * d * 0.125f) + Prow[j] * (1.0f / 6.0f);
        if (s > tv[4]) {
            tv[4] = s; ti[4] = j;
            #pragma unroll
            for (int k = 4; k > 0; k--) {
                if (tv[k] > tv[k-1] || (tv[k] == tv[k-1] && ti[k] < ti[k-1])) {
                    float tf = tv[k]; tv[k] = tv[k-1]; tv[k-1] = tf;
                    int   tt = ti[k]; ti[k] = ti[k-1]; ti[k-1] = tt;
                }
            }
        }
    }
    int pos = 0;
    for (int r = 0; r < 5; r++) {
        float cv = (pos < 5) ? tv[pos] : -1e30f;
        int   ci = (pos < 5) ? ti[pos] : 0x7fffffff;
        float wv = cv; int wi = ci;
        #pragma unroll
        for (int off = 16; off; off >>= 1) {
            float ov = __shfl_xor_sync(0xffffffffu, wv, off);
            int   oi = __shfl_xor_sync(0xffffffffu, wi, off);
            if (ov > wv || (ov == wv && oi < wi)) { wv = ov; wi = oi; }
        }
        if (pos < 5 && ci == wi) pos++;
        if (lane == 0) {
            size_t o = ((size_t)v * B_ * N_ + row) * 5 + r;
            g_topv[o] = wv; g_topi[o] = wi;
        }
    }
}

// ---- den: SYMMETRIC fused exp rowsum. Upper-triangle tiles only; each
// off-diagonal tile adds row sums AND column sums (atomicAdd). Diag excluded.
__global__ void __launch_bounds__(256) den_sym_kernel() {
    __shared__ __align__(16) __nv_bfloat16 As[GBM][GBKP];
    __shared__ __align__(16) __nv_bfloat16 Bs[GBN][GBKP];
    __shared__ float rsm[2][GBM];
    const int tid = threadIdx.x;
    const int wid = tid >> 5, lane = tid & 31;
    const int wm = wid >> 1, wn = wid & 1;
    const int gid = lane >> 2, t4 = lane & 3;
    const int bz = blockIdx.y;
    // triangle decode: blockIdx.x in [0,136) -> (by, jt), jt >= by, 16x16 tiles
    int rem = blockIdx.x, by = 0;
    while (rem >= 16 - by) { rem -= 16 - by; by++; }
    const int jt = by + rem;
    const __nv_bfloat16* Zb = g_zn + (size_t)bz * NC_ * D_;

    float acc[2][8][4];
    #pragma unroll
    for (int mi = 0; mi < 2; mi++)
        #pragma unroll
        for (int ni = 0; ni < 8; ni++)
            #pragma unroll
            for (int q = 0; q < 4; q++) acc[mi][ni][q] = 0.f;

    for (int kb = 0; kb < D_; kb += GBK) {
        #pragma unroll
        for (int u = 0; u < 2; u++) {
            int e = tid + u * 256;
            int r = e >> 2, c8 = e & 3;
            *reinterpret_cast<uint4*>(&As[r][c8 * 8]) =
                *reinterpret_cast<const uint4*>(Zb + (size_t)(by * GBM + r) * D_ + kb + c8 * 8);
            *reinterpret_cast<uint4*>(&Bs[r][c8 * 8]) =
                *reinterpret_cast<const uint4*>(Zb + (size_t)(jt * GBN + r) * D_ + kb + c8 * 8);
        }
        __syncthreads();
        #pragma unroll
        for (int kk = 0; kk < 2; kk++) {
            uint32_t af[2][4], bfr[8][2];
            const int cc = kk * 16 + 2 * t4;
            #pragma unroll
            for (int mi = 0; mi < 2; mi++) {
                int r = wm * 32 + mi * 16 + gid;
                af[mi][0] = *reinterpret_cast<const uint32_t*>(&As[r][cc]);
                af[mi][1] = *reinterpret_cast<const uint32_t*>(&As[r + 8][cc]);
                af[mi][2] = *reinterpret_cast<const uint32_t*>(&As[r][cc + 8]);
                af[mi][3] = *reinterpret_cast<const uint32_t*>(&As[r + 8][cc + 8]);
            }
            #pragma unroll
            for (int ni = 0; ni < 8; ni++) {
                int n = wn * 64 + ni * 8 + gid;
                bfr[ni][0] = *reinterpret_cast<const uint32_t*>(&Bs[n][cc]);
                bfr[ni][1] = *reinterpret_cast<const uint32_t*>(&Bs[n][cc + 8]);
            }
            #pragma unroll
            for (int mi = 0; mi < 2; mi++)
                #pragma unroll
                for (int ni = 0; ni < 8; ni++)
                    mma16816(acc[mi][ni], af[mi], bfr[ni]);
        }
        __syncthreads();
    }

    // exps + row sums + (jt>by) column sums
    float rs[2][2] = {{0.f, 0.f}, {0.f, 0.f}};
    float cs[8][2];
    #pragma unroll
    for (int ni = 0; ni < 8; ni++) cs[ni][0] = cs[ni][1] = 0.f;
    #pragma unroll
    for (int mi = 0; mi < 2; mi++) {
        int rg0 = by * GBM + wm * 32 + mi * 16 + gid;
        #pragma unroll
        for (int ni = 0; ni < 8; ni++) {
            int c0 = jt * GBN + wn * 64 + ni * 8 + 2 * t4;
            float e0 = (rg0     != c0    ) ? __expf(acc[mi][ni][0] * INV_TEMP) : 0.f;
            float e1 = (rg0     != c0 + 1) ? __expf(acc[mi][ni][1] * INV_TEMP) : 0.f;
            float e2 = (rg0 + 8 != c0    ) ? __expf(acc[mi][ni][2] * INV_TEMP) : 0.f;
            float e3 = (rg0 + 8 != c0 + 1) ? __expf(acc[mi][ni][3] * INV_TEMP) : 0.f;
            rs[mi][0] += e0 + e1;
            rs[mi][1] += e2 + e3;
            cs[ni][0] += e0 + e2;
            cs[ni][1] += e1 + e3;
        }
    }
    // row reduce over t4, combine wn halves in smem, atomicAdd
    #pragma unroll
    for (int off = 1; off < 4; off <<= 1) {
        rs[0][0] += __shfl_xor_sync(0xffffffffu, rs[0][0], off);
        rs[0][1] += __shfl_xor_sync(0xffffffffu, rs[0][1], off);
        rs[1][0] += __shfl_xor_sync(0xffffffffu, rs[1][0], off);
        rs[1][1] += __shfl_xor_sync(0xffffffffu, rs[1][1], off);
    }
    if (t4 == 0) {
        #pragma unroll
        for (int mi = 0; mi < 2; mi++) {
            rsm[wn][wm * 32 + mi * 16 + gid]     = rs[mi][0];
            rsm[wn][wm * 32 + mi * 16 + gid + 8] = rs[mi][1];
        }
    }
    __syncthreads();
    if (tid < GBM)
        atomicAdd(&g_den[bz * NC_ + by * GBM + tid], rsm[0][tid] + rsm[1][tid]);

    if (jt > by) {
        // col reduce over gid (lanes 4,8,16), then atomicAdd from gid==0 lanes
        #pragma unroll
        for (int ni = 0; ni < 8; ni++) {
            #pragma unroll
            for (int off = 4; off < 32; off <<= 1) {
                cs[ni][0] += __shfl_xor_sync(0xffffffffu, cs[ni][0], off);
                cs[ni][1] += __shfl_xor_sync(0xffffffffu, cs[ni][1], off);
            }
        }
        if (gid == 0) {
            #pragma unroll
            for (int ni = 0; ni < 8; ni++) {
                int c0 = jt * GBN + wn * 64 + ni * 8 + 2 * t4;
                atomicAdd(&g_den[bz * NC_ + c0],     cs[ni][0]);
                atomicAdd(&g_den[bz * NC_ + c0 + 1], cs[ni][1]);
            }
        }
    }
}

// ---- per-row loss (warp per row), block partial sums ----
__global__ void loss_kernel() {
    __shared__ float wloss[8];
    int lwarp = threadIdx.x >> 5;
    int warp = blockIdx.x * 8 + lwarp;
    int lane = threadIdx.x & 31;
    int b = warp >> 11;
    int i = warp & (NC_ - 1);
    bool half0 = i < N_;
    int ii = half0 ? i : i - N_;
    const __nv_bfloat16* self  = g_zn + ((size_t)b * NC_ + i) * D_;
    const __nv_bfloat16* pbase = g_zn + ((size_t)b * NC_ + (half0 ? N_ : 0)) * D_;
    int v = half0 ? 1 : 0;
    size_t to = (((size_t)v * B_ + b) * N_ + ii) * 5;

    uint4 sv = reinterpret_cast<const uint4*>(self)[lane];
    __nv_bfloat16 ah[8]; memcpy(ah, &sv, 16);
    float af[8];
    #pragma unroll
    for (int k = 0; k < 8; k++) af[k] = __bfloat162float(ah[k]);

    float num = 0.f;
    #pragma unroll
    for (int t = 0; t < 6; t++) {
        int pr; float w;
        if (t == 0) { pr = ii; w = 1.f; }
        else        { pr = g_topi[to + t - 1]; w = g_topv[to + t - 1]; }
        uint4 bv = reinterpret_cast<const uint4*>(pbase + (size_t)pr * D_)[lane];
        __nv_bfloat16 bh[8]; memcpy(bh, &bv, 16);
        float s = 0.f;
        #pragma unroll
        for (int k = 0; k < 8; k++) s += af[k] * __bfloat162float(bh[k]);
        #pragma unroll
        for (int off = 16; off; off >>= 1) s += __shfl_xor_sync(0xffffffffu, s, off);
        float e = expf(s * INV_TEMP);
        if (t == 0) num += e;
        else if (pr != ii) num += w * e;
    }
    if (lane == 0) {
        float den = g_den[b * NC_ + i];
        wloss[lwarp] = -logf(num / (den + 1e-9f) + 1e-9f);
    }
    __syncthreads();
    if (threadIdx.x == 0) {
        float s = 0.f;
        #pragma unroll
        for (int k = 0; k < 8; k++) s += wloss[k];
        g_partial[blockIdx.x] = s;
    }
}

__global__ void reduce_kernel(float* out) {
    int tid = threadIdx.x;
    float s = 0.f;
    for (int k = tid; k < 4096; k += 256) s += g_partial[k];
    #pragma unroll
    for (int off = 16; off; off >>= 1) s += __shfl_xor_sync(0xffffffffu, s, off);
    __shared__ float sm[8];
    if ((tid & 31) == 0) sm[tid >> 5] = s;
    __syncthreads();
    if (tid == 0) {
        float t = 0.f;
        #pragma unroll
        for (int k = 0; k < 8; k++) t += sm[k];
        out[0] = t / (float)(B_ * NC_);
    }
}

// ======================= launch =============================================
extern "C" void kernel_launch(void* const* d_in, const int* in_sizes, int n_in,
                              void* d_out, int out_size) {
    const float* z1 = (const float*)d_in[0];
    const float* z2 = (const float*)d_in[1];
    float* out = (float*)d_out;
    (void)in_sizes; (void)n_in; (void)out_size;

    cudaFuncSetAttribute(pg_gemm<0>, cudaFuncAttributeMaxDynamicSharedMemorySize, GEMM_SMEM);
    cudaFuncSetAttribute(pg_gemm<1>, cudaFuncAttributeMaxDynamicSharedMemorySize, GEMM_SMEM);
    cudaFuncSetAttribute(pg_gemm<2>, cudaFuncAttributeMaxDynamicSharedMemorySize, GEMM_SMEM);

    __nv_bfloat16* znA = nullptr;
    float *simP = nullptr, *pP = nullptr;
    __nv_bfloat16 *aP = nullptr, *atP = nullptr, *a2P = nullptr, *a2tP = nullptr;
    cudaGetSymbolAddress((void**)&znA,  g_zn);
    cudaGetSymbolAddress((void**)&simP, g_sim);
    cudaGetSymbolAddress((void**)&aP,   g_A);
    cudaGetSymbolAddress((void**)&atP,  g_AT);
    cudaGetSymbolAddress((void**)&a2P,  g_A2);
    cudaGetSymbolAddress((void**)&a2tP, g_A2T);
    cudaGetSymbolAddress((void**)&pP,   g_P);

    zden_kernel<<<32, 1024>>>();
    norm_kernel<<<4096, 256>>>(z1, z2);
    nop_kernel<<<1, 32>>>();   // launch #4 below = pg_gemm<0> (ncu window)
    dim3 gg(N_ / GBN, N_ / GBM, B_);
    dim3 gt(16, 16, B_);
    for (int v = 0; v < 2; v++) {
        const __nv_bfloat16* zv = znA + (size_t)v * N_ * D_;
        pg_gemm<0><<<gg, 256, GEMM_SMEM>>>(zv, (size_t)NC_ * D_, zv, (size_t)NC_ * D_,
                                           simP, nullptr, nullptr, (size_t)N_ * N_, D_, N_);
        softmax_kernel<<<2048, 256>>>();
        transpose_kernel<<<gt, 256>>>(aP, atP);
        pg_gemm<1><<<gg, 256, GEMM_SMEM>>>(aP, (size_t)N_ * N_, atP, (size_t)N_ * N_,
                                           nullptr, a2P, pP, (size_t)N_ * N_, N_, N_);
        transpose_kernel<<<gt, 256>>>(a2P, a2tP);
        pg_gemm<2><<<gg, 256, GEMM_SMEM>>>(a2P, (size_t)N_ * N_, a2tP, (size_t)N_ * N_,
                                           nullptr, nullptr, pP, (size_t)N_ * N_, N_, N_);
        topk_kernel<<<2048, 256>>>(v);
    }
    den_sym_kernel<<<dim3(136, B_), 256>>>();
    loss_kernel<<<4096, 256>>>();
    reduce_kernel<<<1, 256>>>(out);
}